// round 13
// baseline (speedup 1.0000x reference)
#include <cuda_runtime.h>

#define W_IMG 3840
#define H_IMG 2160
#define OUT_W 60             // output columns per warp (lane pairs 1..30)
#define NW_X 64              // 3840 / 60
#define NW_Y 74              // vertical strips (30 or 29 rows)
#define WPB 8
#define NTHREADS 256
#define NBLOCKS ((NW_X * NW_Y) / WPB)   // 592 = 148 SMs x 4 blocks, one wave

__device__ double g_num;
__device__ unsigned int g_cnt;
__device__ unsigned int g_ticket;

__constant__ float c_l[27];
__constant__ float c_Kc[9];

__launch_bounds__(NTHREADS, 4)
__global__ void shading_loss_kernel(const float* __restrict__ depth,
                                    const float* __restrict__ rgb,
                                    const int*   __restrict__ mask,
                                    float* __restrict__ out)
{
    const int tid  = threadIdx.x;
    const int lane = tid & 31;
    const int w    = tid >> 5;
    const int wid  = blockIdx.x * WPB + w;
    const int tx   = wid % NW_X;
    const int ty   = wid / NW_X;
    // 2160 = 14*30 + 60*29 : first 14 strips are 30 rows tall
    const int r0   = ty * 29 + min(ty, 14);
    const int hgt  = 29 + (ty < 14 ? 1 : 0);
    const int c0   = tx * OUT_W;
    const int colA = c0 - 2 + 2 * lane;    // even
    const int colB = colA + 1;
    const bool colinA = (colA >= 0) && (colA < W_IMG);
    const bool colinB = (colB >= 0) && (colB < W_IMG);
    const bool safe   = (tx >= 1) && (tx <= NW_X - 2) && (ty >= 1) && (ty <= NW_Y - 2);

    // camera inverse (adjugate) from constant bank — uniform arithmetic
    float a = c_Kc[0], b = c_Kc[1], cc = c_Kc[2];
    float d = c_Kc[3], e = c_Kc[4], f  = c_Kc[5];
    float g = c_Kc[6], h = c_Kc[7], i  = c_Kc[8];
    float A =  (e*i - f*h), B = -(d*i - f*g), C =  (d*h - e*g);
    float inv = 1.0f / (a*A + b*B + cc*C);
    const float K0 = A*inv,  K1 = -(b*i - cc*h)*inv,  K2 =  (b*f - cc*e)*inv;
    const float K3 = B*inv,  K4 =  (a*i - cc*g)*inv,  K5 = -(a*f - cc*d)*inv;
    const float K6 = C*inv,  K7 = -(a*h - b*g)*inv,   K8 =  (a*e - b*d)*inv;

    // ray for column A at row r0-1 (column B ray = ray + (K0,K3,K6))
    const float xA = (float)colA;
    const float y0 = (float)(r0 - 1);
    float rx = K0 * xA + K1 * y0 + K2;
    float ry = K3 * xA + K4 * y0 + K5;
    float rz = K6 * xA + K7 * y0 + K8;

    float acc = 0.0f;
    unsigned int cnt = 0;
    const float emitf = (lane >= 1 && lane <= 30) ? 1.0f : 0.0f;
    const unsigned int ecnt = (lane >= 1 && lane <= 30) ? 1u : 0u;
    const float inv9 = 1.0f / 9.0f;
    const int rend = r0 + hgt;

    // vertical pipeline state
    float h2a0,h2a1,h2a2, h2b0,h2b1,h2b2;   // hsum(row r-2)
    float h1a0,h1a1,h1a2, h1b0,h1b1,h1b2;   // hsum(row r-1)
    float qCa0,qCa1,qCa2, qCb0,qCb1,qCb2;   // q(row r-1)
    float mfaE, mfbE;                        // emit gates for row r-1
    unsigned int cadd;                       // emit count for row r-1
    float dA_a, dA_b;                        // depth(row r)

// branchless shade: always compute SH color for one column
#define SHADE1(bb0,bb1,bb2, rxv,ryv,rzv, d0,dl,du)                            \
  {                                                                           \
    float px=(rxv)*(d0), py=(ryv)*(d0), pz=(rzv)*(d0);                        \
    float axv=((rxv)+K0)*(dl)-px, ayv=((ryv)+K3)*(dl)-py, azv=((rzv)+K6)*(dl)-pz; \
    float bxv=((rxv)+K1)*(du)-px, byv=((ryv)+K4)*(du)-py, bzv=((rzv)+K7)*(du)-pz; \
    float nx=ayv*bzv-azv*byv, ny=azv*bxv-axv*bzv, nz=axv*byv-ayv*bxv;         \
    float nn=nx*nx+ny*ny+nz*nz;                                               \
    float invn=rsqrtf(fmaxf(nn,1e-24f));                                      \
    nx*=invn; ny*=invn; nz*=invn;                                             \
    float nx2=nx*nx, ny2=ny*ny, nz2=nz*nz;                                    \
    float H1=ny,H2=nz,H3=nx,H4=nx*ny,H5=ny*nz;                                \
    float H6=2.f*nz2-nx2-ny2, H7=nz*nx, H8=nx2-ny2;                           \
    bb0=c_l[0]+H1*c_l[3]+H2*c_l[6]+H3*c_l[9]+H4*c_l[12]+H5*c_l[15]+H6*c_l[18]+H7*c_l[21]+H8*c_l[24]; \
    bb1=c_l[1]+H1*c_l[4]+H2*c_l[7]+H3*c_l[10]+H4*c_l[13]+H5*c_l[16]+H6*c_l[19]+H7*c_l[22]+H8*c_l[25]; \
    bb2=c_l[2]+H1*c_l[5]+H2*c_l[8]+H3*c_l[11]+H4*c_l[14]+H5*c_l[17]+H6*c_l[20]+H7*c_l[23]+H8*c_l[26]; \
  }

// shared core: shade both columns, gate by mask (branchless), horizontal sums
#define ROW_CORE(dBa_, dBb_, ma_, mb_, ra0_,ra1_,ra2_, rb0_,rb1_,rb2_)        \
    float dRa = dA_b;                                                         \
    float dRb = __shfl_down_sync(0xffffffffu, dA_a, 1);                       \
    float ba0,ba1,ba2, bbv0,bbv1,bbv2;                                        \
    SHADE1(ba0,ba1,ba2,   rx,ry,rz,          dA_a,dRa,(dBa_));                \
    SHADE1(bbv0,bbv1,bbv2, rx+K0,ry+K3,rz+K6, dA_b,dRb,(dBb_));               \
    float mfa = (ma_) ? 1.0f : 0.0f, mfb = (mb_) ? 1.0f : 0.0f;               \
    float qa0 = fmaf(ba0,  mfa, -(ra0_));                                     \
    float qa1 = fmaf(ba1,  mfa, -(ra1_));                                     \
    float qa2 = fmaf(ba2,  mfa, -(ra2_));                                     \
    float qb0 = fmaf(bbv0, mfb, -(rb0_));                                     \
    float qb1 = fmaf(bbv1, mfb, -(rb1_));                                     \
    float qb2 = fmaf(bbv2, mfb, -(rb2_));                                     \
    float p0 = qa0+qb0, p1 = qa1+qb1, p2 = qa2+qb2;                           \
    float hsa0 = __shfl_up_sync(0xffffffffu, qb0, 1) + p0;                    \
    float hsa1 = __shfl_up_sync(0xffffffffu, qb1, 1) + p1;                    \
    float hsa2 = __shfl_up_sync(0xffffffffu, qb2, 1) + p2;                    \
    float hsb0 = p0 + __shfl_down_sync(0xffffffffu, qa0, 1);                  \
    float hsb1 = p1 + __shfl_down_sync(0xffffffffu, qa1, 1);                  \
    float hsb2 = p2 + __shfl_down_sync(0xffffffffu, qa2, 1);                  \
    dA_a = (dBa_); dA_b = (dBb_);                                             \
    rx += K1; ry += K4; rz += K7;

#define ROW_SAFE                                                              \
    float2 dBv = *reinterpret_cast<const float2*>(depth + off + W_IMG);       \
    int2   mmv = *reinterpret_cast<const int2*>(mask + off);                  \
    const float* rp = rgb + off3;                                             \
    float2 f0 = *reinterpret_cast<const float2*>(rp);                         \
    float2 f1 = *reinterpret_cast<const float2*>(rp + 2);                     \
    float2 f2 = *reinterpret_cast<const float2*>(rp + 4);                     \
    int ma = mmv.x > 0, mb = mmv.y > 0;                                       \
    ROW_CORE(dBv.x, dBv.y, ma, mb, f0.x,f0.y,f1.x, f1.y,f2.x,f2.y);           \
    off += W_IMG; off3 += 3 * W_IMG;

#define ROW_GEN                                                               \
    const bool rin  = ((unsigned)r < (unsigned)H_IMG);                        \
    const bool rnin = ((unsigned)(r + 1) < (unsigned)H_IMG);                  \
    float dBa = (rnin && colinA) ? depth[off + W_IMG]     : 0.0f;             \
    float dBb = (rnin && colinB) ? depth[off + W_IMG + 1] : 0.0f;             \
    int ma = 0, mb = 0;                                                       \
    float ra0=0.f,ra1=0.f,ra2=0.f, rb0=0.f,rb1=0.f,rb2=0.f;                   \
    if (rin && colinA) { ma = mask[off] > 0;                                  \
        ra0 = rgb[off3]; ra1 = rgb[off3+1]; ra2 = rgb[off3+2]; }              \
    if (rin && colinB) { mb = mask[off+1] > 0;                                \
        rb0 = rgb[off3+3]; rb1 = rgb[off3+4]; rb2 = rgb[off3+5]; }            \
    ROW_CORE(dBa, dBb, ma, mb, ra0,ra1,ra2, rb0,rb1,rb2);                     \
    off += W_IMG; off3 += 3 * W_IMG;

#define EMIT                                                                  \
    {                                                                         \
        float da0 = qCa0 - (h2a0 + h1a0 + hsa0) * inv9;                       \
        float da1 = qCa1 - (h2a1 + h1a1 + hsa1) * inv9;                       \
        float da2 = qCa2 - (h2a2 + h1a2 + hsa2) * inv9;                       \
        float dda = da0*da0 + da1*da1 + da2*da2;                              \
        acc = fmaf(dda, mfaE, acc);                                           \
        float db0 = qCb0 - (h2b0 + h1b0 + hsb0) * inv9;                       \
        float db1 = qCb1 - (h2b1 + h1b1 + hsb1) * inv9;                       \
        float db2 = qCb2 - (h2b2 + h1b2 + hsb2) * inv9;                       \
        float ddb = db0*db0 + db1*db1 + db2*db2;                              \
        acc = fmaf(ddb, mfbE, acc);                                           \
        cnt += cadd;                                                          \
    }

#define ROTATE                                                                \
    h2a0=h1a0; h2a1=h1a1; h2a2=h1a2; h2b0=h1b0; h2b1=h1b1; h2b2=h1b2;         \
    h1a0=hsa0; h1a1=hsa1; h1a2=hsa2; h1b0=hsb0; h1b1=hsb1; h1b2=hsb2;         \
    qCa0=qa0; qCa1=qa1; qCa2=qa2; qCb0=qb0; qCb1=qb1; qCb2=qb2;               \
    mfaE = ma ? emitf : 0.0f;                                                 \
    mfbE = mb ? emitf : 0.0f;                                                 \
    cadd = ecnt * (unsigned int)(ma + mb);

    if (safe) {
        int off  = (r0 - 1) * W_IMG + colA;
        int off3 = off * 3;
        float2 dv = *reinterpret_cast<const float2*>(depth + off);
        dA_a = dv.x; dA_b = dv.y;
        // warm-up row r0-1 -> h2
        { ROW_SAFE;
          h2a0=hsa0; h2a1=hsa1; h2a2=hsa2; h2b0=hsb0; h2b1=hsb1; h2b2=hsb2; }
        // warm-up row r0 -> h1, qC, emit gates
        { ROW_SAFE;
          h1a0=hsa0; h1a1=hsa1; h1a2=hsa2; h1b0=hsb0; h1b1=hsb1; h1b2=hsb2;
          qCa0=qa0; qCa1=qa1; qCa2=qa2; qCb0=qb0; qCb1=qb1; qCb2=qb2;
          mfaE = ma ? emitf : 0.0f; mfbE = mb ? emitf : 0.0f;
          cadd = ecnt * (unsigned int)(ma + mb); }
        #pragma unroll 2
        for (int r = r0 + 1; r <= rend; ++r) {
            ROW_SAFE;
            EMIT;
            ROTATE;
        }
    } else {
        int off  = (r0 - 1) * W_IMG + colA;
        int off3 = off * 3;
        dA_a = 0.0f; dA_b = 0.0f;
        if (r0 >= 1) {
            if (colinA) dA_a = depth[off];
            if (colinB) dA_b = depth[off + 1];
        }
        { int r = r0 - 1; ROW_GEN;
          h2a0=hsa0; h2a1=hsa1; h2a2=hsa2; h2b0=hsb0; h2b1=hsb1; h2b2=hsb2; }
        { int r = r0; ROW_GEN;
          h1a0=hsa0; h1a1=hsa1; h1a2=hsa2; h1b0=hsb0; h1b1=hsb1; h1b2=hsb2;
          qCa0=qa0; qCa1=qa1; qCa2=qa2; qCb0=qb0; qCb1=qb1; qCb2=qb2;
          mfaE = ma ? emitf : 0.0f; mfbE = mb ? emitf : 0.0f;
          cadd = ecnt * (unsigned int)(ma + mb); }
        #pragma unroll 1
        for (int r = r0 + 1; r <= rend; ++r) {
            ROW_GEN;
            EMIT;
            ROTATE;
        }
    }

    // ---- reduction: warp -> block -> global ----
    #pragma unroll
    for (int o = 16; o > 0; o >>= 1) {
        acc += __shfl_down_sync(0xffffffffu, acc, o);
        cnt += __shfl_down_sync(0xffffffffu, cnt, o);
    }
    __shared__ float s_red[WPB];
    __shared__ unsigned int s_redc[WPB];
    if (lane == 0) { s_red[w] = acc; s_redc[w] = cnt; }
    __syncthreads();
    if (tid == 0) {
        float aa = 0.0f; unsigned int cn = 0;
        #pragma unroll
        for (int k = 0; k < WPB; k++) { aa += s_red[k]; cn += s_redc[k]; }
        atomicAdd(&g_num, (double)aa);
        atomicAdd(&g_cnt, cn);
        __threadfence();
        unsigned int t = atomicAdd(&g_ticket, 1u);
        if (t == NBLOCKS - 1) {
            __threadfence();
            double num = g_num;
            unsigned int c2 = g_cnt;
            out[0] = (float)(num / ((double)c2 * 3.0));
            g_num = 0.0;
            g_cnt = 0u;
            g_ticket = 0u;
        }
    }
}

extern "C" void kernel_launch(void* const* d_in, const int* in_sizes, int n_in,
                              void* d_out, int out_size) {
    const float* depth = (const float*)d_in[0];
    const float* rgb   = (const float*)d_in[1];
    const int*   mask  = (const int*)d_in[2];
    const float* l     = (const float*)d_in[3];
    const float* Kc    = (const float*)d_in[4];

    cudaMemcpyToSymbolAsync(c_l,  l,  27 * sizeof(float), 0, cudaMemcpyDeviceToDevice);
    cudaMemcpyToSymbolAsync(c_Kc, Kc,  9 * sizeof(float), 0, cudaMemcpyDeviceToDevice);

    shading_loss_kernel<<<NBLOCKS, NTHREADS>>>(depth, rgb, mask, (float*)d_out);
}

// round 14
// speedup vs baseline: 1.1718x; 1.1718x over previous
#include <cuda_runtime.h>

#define W_IMG 3840
#define H_IMG 2160
#define OUT_W 60             // output columns per warp (lane pairs 1..30)
#define NW_X 64              // 3840 / 60
#define NW_Y 74              // vertical strips (30 or 29 rows)
#define WPB 8
#define NTHREADS 256
#define NBLOCKS ((NW_X * NW_Y) / WPB)   // 592 = 148 SMs x 4 blocks, one wave

__device__ double g_num;
__device__ unsigned int g_cnt;
__device__ unsigned int g_ticket;

__constant__ float c_l[27];
__constant__ float c_Kc[9];

__launch_bounds__(NTHREADS, 4)
__global__ void shading_loss_kernel(const float* __restrict__ depth,
                                    const float* __restrict__ rgb,
                                    const int*   __restrict__ mask,
                                    float* __restrict__ out)
{
    const int tid  = threadIdx.x;
    const int lane = tid & 31;
    const int w    = tid >> 5;
    const int wid  = blockIdx.x * WPB + w;
    const int tx   = wid % NW_X;
    const int ty   = wid / NW_X;
    // 2160 = 14*30 + 60*29 : first 14 strips are 30 rows tall
    const int r0   = ty * 29 + min(ty, 14);
    const int hgt  = 29 + (ty < 14 ? 1 : 0);
    const int c0   = tx * OUT_W;
    const int colA = c0 - 2 + 2 * lane;    // even
    const int colB = colA + 1;
    const bool colinA = (colA >= 0) && (colA < W_IMG);
    const bool colinB = (colB >= 0) && (colB < W_IMG);
    const bool safe   = (tx >= 1) && (tx <= NW_X - 2) && (ty >= 1) && (ty <= NW_Y - 2);

    // camera inverse (adjugate) from constant bank — uniform arithmetic
    float a = c_Kc[0], b = c_Kc[1], cc = c_Kc[2];
    float d = c_Kc[3], e = c_Kc[4], f  = c_Kc[5];
    float g = c_Kc[6], h = c_Kc[7], i  = c_Kc[8];
    float A =  (e*i - f*h), B = -(d*i - f*g), C =  (d*h - e*g);
    float inv = 1.0f / (a*A + b*B + cc*C);
    const float K0 = A*inv,  K1 = -(b*i - cc*h)*inv,  K2 =  (b*f - cc*e)*inv;
    const float K3 = B*inv,  K4 =  (a*i - cc*g)*inv,  K5 = -(a*f - cc*d)*inv;
    const float K6 = C*inv,  K7 = -(a*h - b*g)*inv,   K8 =  (a*e - b*d)*inv;

    // ray for column A at row r0-1
    const float xA = (float)colA;
    const float y0 = (float)(r0 - 1);
    float rx = K0 * xA + K1 * y0 + K2;
    float ry = K3 * xA + K4 * y0 + K5;
    float rz = K6 * xA + K7 * y0 + K8;

    float acc = 0.0f;
    unsigned int cnt = 0;
    const bool emitlane = (lane >= 1) && (lane <= 30);
    const float inv9 = 1.0f / 9.0f;
    const int rend = r0 + hgt;

    // vertical pipeline state
    float h2a0,h2a1,h2a2, h2b0,h2b1,h2b2;   // hsum(row r-2)
    float h1a0,h1a1,h1a2, h1b0,h1b1,h1b2;   // hsum(row r-1)
    float qCa0,qCa1,qCa2, qCb0,qCb1,qCb2;   // q(row r-1)
    int   mCa, mCb;
    float dA_a, dA_b;                        // depth(row r)

// shade one column with precomputed center/right/down rays
#define SHADE1(qq0,qq1,qq2, cx,cy,cz, Rx_,Ry_,Rz_, Dx_,Dy_,Dz_, d0,dl,du, mm_, rr0,rr1,rr2) \
  {                                                                           \
    float b0=0.f,b1=0.f,b2=0.f;                                               \
    if (mm_) {                                                                \
      float px=(cx)*(d0), py=(cy)*(d0), pz=(cz)*(d0);                         \
      float axv=fmaf((Rx_),(dl),-px), ayv=fmaf((Ry_),(dl),-py), azv=fmaf((Rz_),(dl),-pz); \
      float bxv=fmaf((Dx_),(du),-px), byv=fmaf((Dy_),(du),-py), bzv=fmaf((Dz_),(du),-pz); \
      float nx=ayv*bzv-azv*byv, ny=azv*bxv-axv*bzv, nz=axv*byv-ayv*bxv;       \
      float nn=nx*nx+ny*ny+nz*nz;                                             \
      float invn=rsqrtf(fmaxf(nn,1e-24f));                                    \
      nx*=invn; ny*=invn; nz*=invn;                                           \
      float nx2=nx*nx, ny2=ny*ny, nz2=nz*nz;                                  \
      float H1=ny,H2=nz,H3=nx,H4=nx*ny,H5=ny*nz;                              \
      float H6=2.f*nz2-nx2-ny2, H7=nz*nx, H8=nx2-ny2;                         \
      b0=c_l[0]+H1*c_l[3]+H2*c_l[6]+H3*c_l[9]+H4*c_l[12]+H5*c_l[15]+H6*c_l[18]+H7*c_l[21]+H8*c_l[24]; \
      b1=c_l[1]+H1*c_l[4]+H2*c_l[7]+H3*c_l[10]+H4*c_l[13]+H5*c_l[16]+H6*c_l[19]+H7*c_l[22]+H8*c_l[25]; \
      b2=c_l[2]+H1*c_l[5]+H2*c_l[8]+H3*c_l[11]+H4*c_l[14]+H5*c_l[17]+H6*c_l[20]+H7*c_l[23]+H8*c_l[26]; \
    }                                                                         \
    qq0=b0-(rr0); qq1=b1-(rr1); qq2=b2-(rr2);                                 \
  }

// shared core: precompute shared rays, shade both columns, horizontal sums
#define ROW_CORE(dBa_, dBb_, ma_, mb_, ra0_,ra1_,ra2_, rb0_,rb1_,rb2_)        \
    float dRa = dA_b;                                                         \
    float dRb = __shfl_down_sync(0xffffffffu, dA_a, 1);                       \
    float rBx = rx + K0, rBy = ry + K3, rBz = rz + K6;   /* B center == A right */ \
    float rnx = rx + K1, rny = ry + K4, rnz = rz + K7;   /* next row == A down  */ \
    float rBRx = rBx + K0, rBRy = rBy + K3, rBRz = rBz + K6; /* B right */    \
    float rBDx = rnx + K0, rBDy = rny + K3, rBDz = rnz + K6; /* B down  */    \
    float qa0,qa1,qa2, qb0,qb1,qb2;                                           \
    SHADE1(qa0,qa1,qa2, rx,ry,rz,    rBx,rBy,rBz,   rnx,rny,rnz,              \
           dA_a,dRa,(dBa_), ma_, ra0_,ra1_,ra2_);                             \
    SHADE1(qb0,qb1,qb2, rBx,rBy,rBz, rBRx,rBRy,rBRz, rBDx,rBDy,rBDz,          \
           dA_b,dRb,(dBb_), mb_, rb0_,rb1_,rb2_);                             \
    float p0 = qa0+qb0, p1 = qa1+qb1, p2 = qa2+qb2;                           \
    float hsa0 = __shfl_up_sync(0xffffffffu, qb0, 1) + p0;                    \
    float hsa1 = __shfl_up_sync(0xffffffffu, qb1, 1) + p1;                    \
    float hsa2 = __shfl_up_sync(0xffffffffu, qb2, 1) + p2;                    \
    float hsb0 = p0 + __shfl_down_sync(0xffffffffu, qa0, 1);                  \
    float hsb1 = p1 + __shfl_down_sync(0xffffffffu, qa1, 1);                  \
    float hsb2 = p2 + __shfl_down_sync(0xffffffffu, qa2, 1);                  \
    dA_a = (dBa_); dA_b = (dBb_);                                             \
    rx = rnx; ry = rny; rz = rnz;

#define ROW_SAFE                                                              \
    float2 dBv = *reinterpret_cast<const float2*>(depth + off + W_IMG);       \
    int2   mmv = *reinterpret_cast<const int2*>(mask + off);                  \
    const float* rp = rgb + off3;                                             \
    float2 f0 = *reinterpret_cast<const float2*>(rp);                         \
    float2 f1 = *reinterpret_cast<const float2*>(rp + 2);                     \
    float2 f2 = *reinterpret_cast<const float2*>(rp + 4);                     \
    int ma = mmv.x > 0, mb = mmv.y > 0;                                       \
    ROW_CORE(dBv.x, dBv.y, ma, mb, f0.x,f0.y,f1.x, f1.y,f2.x,f2.y);           \
    off += W_IMG; off3 += 3 * W_IMG;

#define ROW_GEN                                                               \
    const bool rin  = ((unsigned)r < (unsigned)H_IMG);                        \
    const bool rnin = ((unsigned)(r + 1) < (unsigned)H_IMG);                  \
    float dBa = (rnin && colinA) ? depth[off + W_IMG]     : 0.0f;             \
    float dBb = (rnin && colinB) ? depth[off + W_IMG + 1] : 0.0f;             \
    int ma = 0, mb = 0;                                                       \
    float ra0=0.f,ra1=0.f,ra2=0.f, rb0=0.f,rb1=0.f,rb2=0.f;                   \
    if (rin && colinA) { ma = mask[off] > 0;                                  \
        ra0 = rgb[off3]; ra1 = rgb[off3+1]; ra2 = rgb[off3+2]; }              \
    if (rin && colinB) { mb = mask[off+1] > 0;                                \
        rb0 = rgb[off3+3]; rb1 = rgb[off3+4]; rb2 = rgb[off3+5]; }            \
    ROW_CORE(dBa, dBb, ma, mb, ra0,ra1,ra2, rb0,rb1,rb2);                     \
    off += W_IMG; off3 += 3 * W_IMG;

#define EMIT                                                                  \
    if (emitlane) {                                                           \
        if (mCa) {                                                            \
            float t0 = h2a0 + h1a0 + hsa0;                                    \
            float t1 = h2a1 + h1a1 + hsa1;                                    \
            float t2 = h2a2 + h1a2 + hsa2;                                    \
            float d0 = fmaf(t0, -inv9, qCa0);                                 \
            float d1 = fmaf(t1, -inv9, qCa1);                                 \
            float d2 = fmaf(t2, -inv9, qCa2);                                 \
            acc += d0*d0 + d1*d1 + d2*d2;                                     \
            cnt += 1u;                                                        \
        }                                                                     \
        if (mCb) {                                                            \
            float t0 = h2b0 + h1b0 + hsb0;                                    \
            float t1 = h2b1 + h1b1 + hsb1;                                    \
            float t2 = h2b2 + h1b2 + hsb2;                                    \
            float d0 = fmaf(t0, -inv9, qCb0);                                 \
            float d1 = fmaf(t1, -inv9, qCb1);                                 \
            float d2 = fmaf(t2, -inv9, qCb2);                                 \
            acc += d0*d0 + d1*d1 + d2*d2;                                     \
            cnt += 1u;                                                        \
        }                                                                     \
    }

#define ROTATE                                                                \
    h2a0=h1a0; h2a1=h1a1; h2a2=h1a2; h2b0=h1b0; h2b1=h1b1; h2b2=h1b2;         \
    h1a0=hsa0; h1a1=hsa1; h1a2=hsa2; h1b0=hsb0; h1b1=hsb1; h1b2=hsb2;         \
    qCa0=qa0; qCa1=qa1; qCa2=qa2; qCb0=qb0; qCb1=qb1; qCb2=qb2;               \
    mCa=ma; mCb=mb;

    if (safe) {
        int off  = (r0 - 1) * W_IMG + colA;
        int off3 = off * 3;
        float2 dv = *reinterpret_cast<const float2*>(depth + off);
        dA_a = dv.x; dA_b = dv.y;
        // warm-up row r0-1 -> h2
        { ROW_SAFE;
          h2a0=hsa0; h2a1=hsa1; h2a2=hsa2; h2b0=hsb0; h2b1=hsb1; h2b2=hsb2;
          (void)ma; (void)mb; }
        // warm-up row r0 -> h1, qC, mC
        { ROW_SAFE;
          h1a0=hsa0; h1a1=hsa1; h1a2=hsa2; h1b0=hsb0; h1b1=hsb1; h1b2=hsb2;
          qCa0=qa0; qCa1=qa1; qCa2=qa2; qCb0=qb0; qCb1=qb1; qCb2=qb2;
          mCa=ma; mCb=mb; }
        #pragma unroll 2
        for (int r = r0 + 1; r <= rend; ++r) {
            ROW_SAFE;
            EMIT;
            ROTATE;
        }
    } else {
        int off  = (r0 - 1) * W_IMG + colA;
        int off3 = off * 3;
        dA_a = 0.0f; dA_b = 0.0f;
        if (r0 >= 1) {
            if (colinA) dA_a = depth[off];
            if (colinB) dA_b = depth[off + 1];
        }
        { int r = r0 - 1; ROW_GEN;
          h2a0=hsa0; h2a1=hsa1; h2a2=hsa2; h2b0=hsb0; h2b1=hsb1; h2b2=hsb2;
          (void)ma; (void)mb; }
        { int r = r0; ROW_GEN;
          h1a0=hsa0; h1a1=hsa1; h1a2=hsa2; h1b0=hsb0; h1b1=hsb1; h1b2=hsb2;
          qCa0=qa0; qCa1=qa1; qCa2=qa2; qCb0=qb0; qCb1=qb1; qCb2=qb2;
          mCa=ma; mCb=mb; }
        #pragma unroll 1
        for (int r = r0 + 1; r <= rend; ++r) {
            ROW_GEN;
            EMIT;
            ROTATE;
        }
    }

    // ---- reduction: warp -> block -> global ----
    #pragma unroll
    for (int o = 16; o > 0; o >>= 1) {
        acc += __shfl_down_sync(0xffffffffu, acc, o);
        cnt += __shfl_down_sync(0xffffffffu, cnt, o);
    }
    __shared__ float s_red[WPB];
    __shared__ unsigned int s_redc[WPB];
    if (lane == 0) { s_red[w] = acc; s_redc[w] = cnt; }
    __syncthreads();
    if (tid == 0) {
        float aa = 0.0f; unsigned int cn = 0;
        #pragma unroll
        for (int k = 0; k < WPB; k++) { aa += s_red[k]; cn += s_redc[k]; }
        atomicAdd(&g_num, (double)aa);
        atomicAdd(&g_cnt, cn);
        __threadfence();
        unsigned int t = atomicAdd(&g_ticket, 1u);
        if (t == NBLOCKS - 1) {
            __threadfence();
            double num = g_num;
            unsigned int c2 = g_cnt;
            out[0] = (float)(num / ((double)c2 * 3.0));
            g_num = 0.0;
            g_cnt = 0u;
            g_ticket = 0u;
        }
    }
}

extern "C" void kernel_launch(void* const* d_in, const int* in_sizes, int n_in,
                              void* d_out, int out_size) {
    const float* depth = (const float*)d_in[0];
    const float* rgb   = (const float*)d_in[1];
    const int*   mask  = (const int*)d_in[2];
    const float* l     = (const float*)d_in[3];
    const float* Kc    = (const float*)d_in[4];

    cudaMemcpyToSymbolAsync(c_l,  l,  27 * sizeof(float), 0, cudaMemcpyDeviceToDevice);
    cudaMemcpyToSymbolAsync(c_Kc, Kc,  9 * sizeof(float), 0, cudaMemcpyDeviceToDevice);

    shading_loss_kernel<<<NBLOCKS, NTHREADS>>>(depth, rgb, mask, (float*)d_out);
}

// round 15
// speedup vs baseline: 1.2258x; 1.0461x over previous
#include <cuda_runtime.h>

#define W_IMG 3840
#define H_IMG 2160
#define OUT_W 60             // output columns per warp (lane pairs 1..30)
#define NW_X 64              // 3840 / 60
#define NW_Y 74              // vertical strips (30 or 29 rows)
#define WPB 8
#define NTHREADS 256
#define NBLOCKS ((NW_X * NW_Y) / WPB)   // 592 = 148 SMs x 4 blocks, one wave

__device__ double g_num;
__device__ unsigned int g_cnt;
__device__ unsigned int g_ticket;

__constant__ float c_l[27];
__constant__ float c_Kc[9];

__launch_bounds__(NTHREADS, 4)
__global__ void shading_loss_kernel(const float* __restrict__ depth,
                                    const float* __restrict__ rgb,
                                    const int*   __restrict__ mask,
                                    float* __restrict__ out)
{
    const int tid  = threadIdx.x;
    const int lane = tid & 31;
    const int w    = tid >> 5;
    const int wid  = blockIdx.x * WPB + w;
    const int tx   = wid % NW_X;
    const int ty   = wid / NW_X;
    // 2160 = 14*30 + 60*29 : first 14 strips are 30 rows tall
    const int r0   = ty * 29 + min(ty, 14);
    const int hgt  = 29 + (ty < 14 ? 1 : 0);
    const int c0   = tx * OUT_W;
    const int colA = c0 - 2 + 2 * lane;    // even
    const int colB = colA + 1;
    const bool colinA = (colA >= 0) && (colA < W_IMG);
    const bool colinB = (colB >= 0) && (colB < W_IMG);
    const bool safe   = (tx >= 1) && (tx <= NW_X - 2) && (ty >= 1) && (ty <= NW_Y - 2);

    // camera inverse (adjugate) from constant bank — uniform arithmetic
    float a = c_Kc[0], b = c_Kc[1], cc = c_Kc[2];
    float d = c_Kc[3], e = c_Kc[4], f  = c_Kc[5];
    float g = c_Kc[6], h = c_Kc[7], i  = c_Kc[8];
    float A =  (e*i - f*h), B = -(d*i - f*g), C =  (d*h - e*g);
    float inv = 1.0f / (a*A + b*B + cc*C);
    const float K0 = A*inv,  K1 = -(b*i - cc*h)*inv,  K2 =  (b*f - cc*e)*inv;
    const float K3 = B*inv,  K4 =  (a*i - cc*g)*inv,  K5 = -(a*f - cc*d)*inv;
    const float K6 = C*inv,  K7 = -(a*h - b*g)*inv,   K8 =  (a*e - b*d)*inv;

    // ray for column A at row r0-1
    const float xA = (float)colA;
    const float y0 = (float)(r0 - 1);
    float rx = K0 * xA + K1 * y0 + K2;
    float ry = K3 * xA + K4 * y0 + K5;
    float rz = K6 * xA + K7 * y0 + K8;

    float acc = 0.0f;
    unsigned int cnt = 0;
    const bool emitlane = (lane >= 1) && (lane <= 30);
    const float inv9 = 1.0f / 9.0f;
    const int rend = r0 + hgt;

    // vertical pipeline state (u = h(r-2)+h(r-1), v = h(r-1))
    float uA0,uA1,uA2, uB0,uB1,uB2;
    float vA0,vA1,vA2, vB0,vB1,vB2;
    float qCa0,qCa1,qCa2, qCb0,qCb1,qCb2;   // q(row r-1)
    int   mCa, mCb;
    float dA_a, dA_b;                        // depth(row r)

// shade one column with precomputed center/right/down rays
#define SHADE1(qq0,qq1,qq2, cx,cy,cz, Rx_,Ry_,Rz_, Dx_,Dy_,Dz_, d0,dl,du, mm_, rr0,rr1,rr2) \
  {                                                                           \
    float b0=0.f,b1=0.f,b2=0.f;                                               \
    if (mm_) {                                                                \
      float px=(cx)*(d0), py=(cy)*(d0), pz=(cz)*(d0);                         \
      float axv=fmaf((Rx_),(dl),-px), ayv=fmaf((Ry_),(dl),-py), azv=fmaf((Rz_),(dl),-pz); \
      float bxv=fmaf((Dx_),(du),-px), byv=fmaf((Dy_),(du),-py), bzv=fmaf((Dz_),(du),-pz); \
      float nx=ayv*bzv-azv*byv, ny=azv*bxv-axv*bzv, nz=axv*byv-ayv*bxv;       \
      float nn=nx*nx+ny*ny+nz*nz;                                             \
      float invn=rsqrtf(fmaxf(nn,1e-24f));                                    \
      nx*=invn; ny*=invn; nz*=invn;                                           \
      float nx2=nx*nx, ny2=ny*ny, nz2=nz*nz;                                  \
      float H1=ny,H2=nz,H3=nx,H4=nx*ny,H5=ny*nz;                              \
      float H6=2.f*nz2-nx2-ny2, H7=nz*nx, H8=nx2-ny2;                         \
      b0=c_l[0]+H1*c_l[3]+H2*c_l[6]+H3*c_l[9]+H4*c_l[12]+H5*c_l[15]+H6*c_l[18]+H7*c_l[21]+H8*c_l[24]; \
      b1=c_l[1]+H1*c_l[4]+H2*c_l[7]+H3*c_l[10]+H4*c_l[13]+H5*c_l[16]+H6*c_l[19]+H7*c_l[22]+H8*c_l[25]; \
      b2=c_l[2]+H1*c_l[5]+H2*c_l[8]+H3*c_l[11]+H4*c_l[14]+H5*c_l[17]+H6*c_l[20]+H7*c_l[23]+H8*c_l[26]; \
    }                                                                         \
    qq0=b0-(rr0); qq1=b1-(rr1); qq2=b2-(rr2);                                 \
  }

// shared core: precompute shared rays, shade both columns, horizontal sums
#define ROW_CORE(dBa_, dBb_, ma_, mb_, ra0_,ra1_,ra2_, rb0_,rb1_,rb2_)        \
    float dRa = dA_b;                                                         \
    float dRb = __shfl_down_sync(0xffffffffu, dA_a, 1);                       \
    float rBx = rx + K0, rBy = ry + K3, rBz = rz + K6;   /* B center == A right */ \
    float rnx = rx + K1, rny = ry + K4, rnz = rz + K7;   /* next row == A down  */ \
    float rBRx = rBx + K0, rBRy = rBy + K3, rBRz = rBz + K6; /* B right */    \
    float rBDx = rnx + K0, rBDy = rny + K3, rBDz = rnz + K6; /* B down  */    \
    float qa0,qa1,qa2, qb0,qb1,qb2;                                           \
    SHADE1(qa0,qa1,qa2, rx,ry,rz,    rBx,rBy,rBz,   rnx,rny,rnz,              \
           dA_a,dRa,(dBa_), ma_, ra0_,ra1_,ra2_);                             \
    SHADE1(qb0,qb1,qb2, rBx,rBy,rBz, rBRx,rBRy,rBRz, rBDx,rBDy,rBDz,          \
           dA_b,dRb,(dBb_), mb_, rb0_,rb1_,rb2_);                             \
    float p0 = qa0+qb0, p1 = qa1+qb1, p2 = qa2+qb2;                           \
    float hsa0 = __shfl_up_sync(0xffffffffu, qb0, 1) + p0;                    \
    float hsa1 = __shfl_up_sync(0xffffffffu, qb1, 1) + p1;                    \
    float hsa2 = __shfl_up_sync(0xffffffffu, qb2, 1) + p2;                    \
    float hsb0 = p0 + __shfl_down_sync(0xffffffffu, qa0, 1);                  \
    float hsb1 = p1 + __shfl_down_sync(0xffffffffu, qa1, 1);                  \
    float hsb2 = p2 + __shfl_down_sync(0xffffffffu, qa2, 1);                  \
    dA_a = (dBa_); dA_b = (dBb_);                                             \
    rx = rnx; ry = rny; rz = rnz;

#define ROW_SAFE                                                              \
    float2 dBv = *reinterpret_cast<const float2*>(depth + off + W_IMG);       \
    int2   mmv = *reinterpret_cast<const int2*>(mask + off);                  \
    const float* rp = rgb + off3;                                             \
    float2 f0 = *reinterpret_cast<const float2*>(rp);                         \
    float2 f1 = *reinterpret_cast<const float2*>(rp + 2);                     \
    float2 f2 = *reinterpret_cast<const float2*>(rp + 4);                     \
    int ma = mmv.x > 0, mb = mmv.y > 0;                                       \
    ROW_CORE(dBv.x, dBv.y, ma, mb, f0.x,f0.y,f1.x, f1.y,f2.x,f2.y);           \
    off += W_IMG; off3 += 3 * W_IMG;

#define ROW_GEN                                                               \
    const bool rin  = ((unsigned)r < (unsigned)H_IMG);                        \
    const bool rnin = ((unsigned)(r + 1) < (unsigned)H_IMG);                  \
    float dBa = (rnin && colinA) ? depth[off + W_IMG]     : 0.0f;             \
    float dBb = (rnin && colinB) ? depth[off + W_IMG + 1] : 0.0f;             \
    int ma = 0, mb = 0;                                                       \
    float ra0=0.f,ra1=0.f,ra2=0.f, rb0=0.f,rb1=0.f,rb2=0.f;                   \
    if (rin && colinA) { ma = mask[off] > 0;                                  \
        ra0 = rgb[off3]; ra1 = rgb[off3+1]; ra2 = rgb[off3+2]; }              \
    if (rin && colinB) { mb = mask[off+1] > 0;                                \
        rb0 = rgb[off3+3]; rb1 = rgb[off3+4]; rb2 = rgb[off3+5]; }            \
    ROW_CORE(dBa, dBb, ma, mb, ra0,ra1,ra2, rb0,rb1,rb2);                     \
    off += W_IMG; off3 += 3 * W_IMG;

// emit row r-1: needs t = u + hs(current row)
#define EMIT                                                                  \
    if (emitlane) {                                                           \
        if (mCa) {                                                            \
            float t0 = uA0 + hsa0;                                            \
            float t1 = uA1 + hsa1;                                            \
            float t2 = uA2 + hsa2;                                            \
            float d0 = fmaf(t0, -inv9, qCa0);                                 \
            float d1 = fmaf(t1, -inv9, qCa1);                                 \
            float d2 = fmaf(t2, -inv9, qCa2);                                 \
            acc += d0*d0 + d1*d1 + d2*d2;                                     \
            cnt += 1u;                                                        \
        }                                                                     \
        if (mCb) {                                                            \
            float t0 = uB0 + hsb0;                                            \
            float t1 = uB1 + hsb1;                                            \
            float t2 = uB2 + hsb2;                                            \
            float d0 = fmaf(t0, -inv9, qCb0);                                 \
            float d1 = fmaf(t1, -inv9, qCb1);                                 \
            float d2 = fmaf(t2, -inv9, qCb2);                                 \
            acc += d0*d0 + d1*d1 + d2*d2;                                     \
            cnt += 1u;                                                        \
        }                                                                     \
    }

// u' = v + hs ; v' = hs   (period-2 rotation: renames fully under unroll 2)
#define ROTATE                                                                \
    uA0 = vA0 + hsa0; uA1 = vA1 + hsa1; uA2 = vA2 + hsa2;                     \
    uB0 = vB0 + hsb0; uB1 = vB1 + hsb1; uB2 = vB2 + hsb2;                     \
    vA0 = hsa0; vA1 = hsa1; vA2 = hsa2;                                       \
    vB0 = hsb0; vB1 = hsb1; vB2 = hsb2;                                       \
    qCa0=qa0; qCa1=qa1; qCa2=qa2; qCb0=qb0; qCb1=qb1; qCb2=qb2;               \
    mCa=ma; mCb=mb;

    if (safe) {
        int off  = (r0 - 1) * W_IMG + colA;
        int off3 = off * 3;
        float2 dv = *reinterpret_cast<const float2*>(depth + off);
        dA_a = dv.x; dA_b = dv.y;
        // warm-up row r0-1 -> v (hs of row r0-1)
        { ROW_SAFE;
          vA0=hsa0; vA1=hsa1; vA2=hsa2; vB0=hsb0; vB1=hsb1; vB2=hsb2;
          (void)ma; (void)mb; }
        // warm-up row r0 -> u = h(r0-1)+h(r0), v = h(r0), qC, mC
        { ROW_SAFE;
          uA0 = vA0 + hsa0; uA1 = vA1 + hsa1; uA2 = vA2 + hsa2;
          uB0 = vB0 + hsb0; uB1 = vB1 + hsb1; uB2 = vB2 + hsb2;
          vA0=hsa0; vA1=hsa1; vA2=hsa2; vB0=hsb0; vB1=hsb1; vB2=hsb2;
          qCa0=qa0; qCa1=qa1; qCa2=qa2; qCb0=qb0; qCb1=qb1; qCb2=qb2;
          mCa=ma; mCb=mb; }
        #pragma unroll 2
        for (int r = r0 + 1; r <= rend; ++r) {
            ROW_SAFE;
            EMIT;
            ROTATE;
        }
    } else {
        int off  = (r0 - 1) * W_IMG + colA;
        int off3 = off * 3;
        dA_a = 0.0f; dA_b = 0.0f;
        if (r0 >= 1) {
            if (colinA) dA_a = depth[off];
            if (colinB) dA_b = depth[off + 1];
        }
        { int r = r0 - 1; ROW_GEN;
          vA0=hsa0; vA1=hsa1; vA2=hsa2; vB0=hsb0; vB1=hsb1; vB2=hsb2;
          (void)ma; (void)mb; }
        { int r = r0; ROW_GEN;
          uA0 = vA0 + hsa0; uA1 = vA1 + hsa1; uA2 = vA2 + hsa2;
          uB0 = vB0 + hsb0; uB1 = vB1 + hsb1; uB2 = vB2 + hsb2;
          vA0=hsa0; vA1=hsa1; vA2=hsa2; vB0=hsb0; vB1=hsb1; vB2=hsb2;
          qCa0=qa0; qCa1=qa1; qCa2=qa2; qCb0=qb0; qCb1=qb1; qCb2=qb2;
          mCa=ma; mCb=mb; }
        #pragma unroll 1
        for (int r = r0 + 1; r <= rend; ++r) {
            ROW_GEN;
            EMIT;
            ROTATE;
        }
    }

    // ---- reduction: warp -> block -> global ----
    #pragma unroll
    for (int o = 16; o > 0; o >>= 1) {
        acc += __shfl_down_sync(0xffffffffu, acc, o);
        cnt += __shfl_down_sync(0xffffffffu, cnt, o);
    }
    __shared__ float s_red[WPB];
    __shared__ unsigned int s_redc[WPB];
    if (lane == 0) { s_red[w] = acc; s_redc[w] = cnt; }
    __syncthreads();
    if (tid == 0) {
        float aa = 0.0f; unsigned int cn = 0;
        #pragma unroll
        for (int k = 0; k < WPB; k++) { aa += s_red[k]; cn += s_redc[k]; }
        atomicAdd(&g_num, (double)aa);
        atomicAdd(&g_cnt, cn);
        __threadfence();
        unsigned int t = atomicAdd(&g_ticket, 1u);
        if (t == NBLOCKS - 1) {
            __threadfence();
            double num = g_num;
            unsigned int c2 = g_cnt;
            out[0] = (float)(num / ((double)c2 * 3.0));
            g_num = 0.0;
            g_cnt = 0u;
            g_ticket = 0u;
        }
    }
}

extern "C" void kernel_launch(void* const* d_in, const int* in_sizes, int n_in,
                              void* d_out, int out_size) {
    const float* depth = (const float*)d_in[0];
    const float* rgb   = (const float*)d_in[1];
    const int*   mask  = (const int*)d_in[2];
    const float* l     = (const float*)d_in[3];
    const float* Kc    = (const float*)d_in[4];

    cudaMemcpyToSymbolAsync(c_l,  l,  27 * sizeof(float), 0, cudaMemcpyDeviceToDevice);
    cudaMemcpyToSymbolAsync(c_Kc, Kc,  9 * sizeof(float), 0, cudaMemcpyDeviceToDevice);

    shading_loss_kernel<<<NBLOCKS, NTHREADS>>>(depth, rgb, mask, (float*)d_out);
}

// round 16
// speedup vs baseline: 1.2452x; 1.0158x over previous
#include <cuda_runtime.h>

#define W_IMG 3840
#define H_IMG 2160
#define OUT_W 60             // output columns per warp (lane pairs 1..30)
#define NW_X 64              // 3840 / 60
#define NW_Y 74              // vertical strips (30 or 29 rows)
#define WPB 8
#define NTHREADS 256
#define NBLOCKS ((NW_X * NW_Y) / WPB)   // 592 = 148 SMs x 4 blocks, one wave

__device__ double g_num;
__device__ unsigned int g_cnt;
__device__ unsigned int g_ticket;

__constant__ float c_l[27];
__constant__ float c_Kc[9];

__launch_bounds__(NTHREADS, 4)
__global__ void shading_loss_kernel(const float* __restrict__ depth,
                                    const float* __restrict__ rgb,
                                    const int*   __restrict__ mask,
                                    float* __restrict__ out)
{
    const int tid  = threadIdx.x;
    const int lane = tid & 31;
    const int w    = tid >> 5;
    const int wid  = blockIdx.x * WPB + w;
    const int tx   = wid % NW_X;
    const int ty   = wid / NW_X;
    // 2160 = 14*30 + 60*29 : first 14 strips are 30 rows tall
    const int r0   = ty * 29 + min(ty, 14);
    const int hgt  = 29 + (ty < 14 ? 1 : 0);
    const int c0   = tx * OUT_W;
    const int colA = c0 - 2 + 2 * lane;    // even
    const int colB = colA + 1;
    const bool colinA = (colA >= 0) && (colA < W_IMG);
    const bool colinB = (colB >= 0) && (colB < W_IMG);
    const bool safe   = (tx >= 1) && (tx <= NW_X - 2) && (ty >= 1) && (ty <= NW_Y - 2);

    // camera inverse (adjugate) from constant bank — uniform arithmetic
    float a = c_Kc[0], b = c_Kc[1], cc = c_Kc[2];
    float d = c_Kc[3], e = c_Kc[4], f  = c_Kc[5];
    float g = c_Kc[6], h = c_Kc[7], i  = c_Kc[8];
    float A =  (e*i - f*h), B = -(d*i - f*g), C =  (d*h - e*g);
    float inv = 1.0f / (a*A + b*B + cc*C);
    const float K0 = A*inv,  K1 = -(b*i - cc*h)*inv,  K2 =  (b*f - cc*e)*inv;
    const float K3 = B*inv,  K4 =  (a*i - cc*g)*inv,  K5 = -(a*f - cc*d)*inv;
    const float K6 = C*inv,  K7 = -(a*h - b*g)*inv,   K8 =  (a*e - b*d)*inv;

    // ray for column A at row r0-1
    const float xA = (float)colA;
    const float y0f = (float)(r0 - 1);
    const float Rx = K0 * xA + K1 * y0f + K2;
    const float Ry = K3 * xA + K4 * y0f + K5;
    const float Rz = K6 * xA + K7 * y0f + K8;

    // n = u*[dl(d0-du)] + v*[du(dl-d0)] + w*[dl*du]
    // u = R x e0 : shared by columns A,B; updates u -= w per row.
    // v = R x e1 : constant down column; vB = vA + w.
    // w = e0 x e1 : uniform constant.
    float ux = Ry * K6 - Rz * K3;
    float uy = Rz * K0 - Rx * K6;
    float uz = Rx * K3 - Ry * K0;
    const float wx = K3 * K7 - K6 * K4;
    const float wy = K6 * K1 - K0 * K7;
    const float wz = K0 * K4 - K3 * K1;
    const float vAx = Ry * K7 - Rz * K4;
    const float vAy = Rz * K1 - Rx * K7;
    const float vAz = Rx * K4 - Ry * K1;
    const float vBx = vAx + wx, vBy = vAy + wy, vBz = vAz + wz;

    float acc = 0.0f;
    unsigned int cnt = 0;
    const bool emitlane = (lane >= 1) && (lane <= 30);
    const float inv9 = 1.0f / 9.0f;
    const int rend = r0 + hgt;

    // vertical pipeline state (u-sum recurrence)
    float uA0,uA1,uA2, uB0,uB1,uB2;         // h(r-2)+h(r-1)
    float vA0,vA1,vA2, vB0,vB1,vB2;         // h(r-1)
    float qCa0,qCa1,qCa2, qCb0,qCb1,qCb2;   // q(row r-1)
    int   mCa, mCb;
    float dA_a, dA_b;                        // depth(row r)

// shade one column via the cross-product identity
#define SHADE1(qq0,qq1,qq2, vx_,vy_,vz_, d0,dl,du, mm_, rr0,rr1,rr2)          \
  {                                                                           \
    float b0=0.f,b1=0.f,b2=0.f;                                               \
    if (mm_) {                                                                \
      float s1 = (dl) * ((d0) - (du));                                        \
      float s2 = (du) * ((dl) - (d0));                                        \
      float s3 = (dl) * (du);                                                 \
      float nx = fmaf(ux, s1, fmaf((vx_), s2, wx * s3));                      \
      float ny = fmaf(uy, s1, fmaf((vy_), s2, wy * s3));                      \
      float nz = fmaf(uz, s1, fmaf((vz_), s2, wz * s3));                      \
      float nn=nx*nx+ny*ny+nz*nz;                                             \
      float invn=rsqrtf(fmaxf(nn,1e-24f));                                    \
      nx*=invn; ny*=invn; nz*=invn;                                           \
      float nx2=nx*nx, ny2=ny*ny, nz2=nz*nz;                                  \
      float H1=ny,H2=nz,H3=nx,H4=nx*ny,H5=ny*nz;                              \
      float H6=2.f*nz2-nx2-ny2, H7=nz*nx, H8=nx2-ny2;                         \
      b0=c_l[0]+H1*c_l[3]+H2*c_l[6]+H3*c_l[9]+H4*c_l[12]+H5*c_l[15]+H6*c_l[18]+H7*c_l[21]+H8*c_l[24]; \
      b1=c_l[1]+H1*c_l[4]+H2*c_l[7]+H3*c_l[10]+H4*c_l[13]+H5*c_l[16]+H6*c_l[19]+H7*c_l[22]+H8*c_l[25]; \
      b2=c_l[2]+H1*c_l[5]+H2*c_l[8]+H3*c_l[11]+H4*c_l[14]+H5*c_l[17]+H6*c_l[20]+H7*c_l[23]+H8*c_l[26]; \
    }                                                                         \
    qq0=b0-(rr0); qq1=b1-(rr1); qq2=b2-(rr2);                                 \
  }

// shared core: shade both columns (shared u), horizontal sums, advance u
#define ROW_CORE(dBa_, dBb_, ma_, mb_, ra0_,ra1_,ra2_, rb0_,rb1_,rb2_)        \
    float dRa = dA_b;                                                         \
    float dRb = __shfl_down_sync(0xffffffffu, dA_a, 1);                       \
    float qa0,qa1,qa2, qb0,qb1,qb2;                                           \
    SHADE1(qa0,qa1,qa2, vAx,vAy,vAz, dA_a,dRa,(dBa_), ma_, ra0_,ra1_,ra2_);   \
    SHADE1(qb0,qb1,qb2, vBx,vBy,vBz, dA_b,dRb,(dBb_), mb_, rb0_,rb1_,rb2_);   \
    float p0 = qa0+qb0, p1 = qa1+qb1, p2 = qa2+qb2;                           \
    float hsa0 = __shfl_up_sync(0xffffffffu, qb0, 1) + p0;                    \
    float hsa1 = __shfl_up_sync(0xffffffffu, qb1, 1) + p1;                    \
    float hsa2 = __shfl_up_sync(0xffffffffu, qb2, 1) + p2;                    \
    float hsb0 = p0 + __shfl_down_sync(0xffffffffu, qa0, 1);                  \
    float hsb1 = p1 + __shfl_down_sync(0xffffffffu, qa1, 1);                  \
    float hsb2 = p2 + __shfl_down_sync(0xffffffffu, qa2, 1);                  \
    dA_a = (dBa_); dA_b = (dBb_);                                             \
    ux -= wx; uy -= wy; uz -= wz;

#define ROW_SAFE                                                              \
    float2 dBv = *reinterpret_cast<const float2*>(depth + off + W_IMG);       \
    int2   mmv = *reinterpret_cast<const int2*>(mask + off);                  \
    const float* rp = rgb + off3;                                             \
    float2 f0 = *reinterpret_cast<const float2*>(rp);                         \
    float2 f1 = *reinterpret_cast<const float2*>(rp + 2);                     \
    float2 f2 = *reinterpret_cast<const float2*>(rp + 4);                     \
    int ma = mmv.x > 0, mb = mmv.y > 0;                                       \
    ROW_CORE(dBv.x, dBv.y, ma, mb, f0.x,f0.y,f1.x, f1.y,f2.x,f2.y);           \
    off += W_IMG; off3 += 3 * W_IMG;

#define ROW_GEN                                                               \
    const bool rin  = ((unsigned)r < (unsigned)H_IMG);                        \
    const bool rnin = ((unsigned)(r + 1) < (unsigned)H_IMG);                  \
    float dBa = (rnin && colinA) ? depth[off + W_IMG]     : 0.0f;             \
    float dBb = (rnin && colinB) ? depth[off + W_IMG + 1] : 0.0f;             \
    int ma = 0, mb = 0;                                                       \
    float ra0=0.f,ra1=0.f,ra2=0.f, rb0=0.f,rb1=0.f,rb2=0.f;                   \
    if (rin && colinA) { ma = mask[off] > 0;                                  \
        ra0 = rgb[off3]; ra1 = rgb[off3+1]; ra2 = rgb[off3+2]; }              \
    if (rin && colinB) { mb = mask[off+1] > 0;                                \
        rb0 = rgb[off3+3]; rb1 = rgb[off3+4]; rb2 = rgb[off3+5]; }            \
    ROW_CORE(dBa, dBb, ma, mb, ra0,ra1,ra2, rb0,rb1,rb2);                     \
    off += W_IMG; off3 += 3 * W_IMG;

// emit row r-1: t = u + hs(current row)
#define EMIT                                                                  \
    if (emitlane) {                                                           \
        if (mCa) {                                                            \
            float t0 = uA0 + hsa0;                                            \
            float t1 = uA1 + hsa1;                                            \
            float t2 = uA2 + hsa2;                                            \
            float d0 = fmaf(t0, -inv9, qCa0);                                 \
            float d1 = fmaf(t1, -inv9, qCa1);                                 \
            float d2 = fmaf(t2, -inv9, qCa2);                                 \
            acc += d0*d0 + d1*d1 + d2*d2;                                     \
            cnt += 1u;                                                        \
        }                                                                     \
        if (mCb) {                                                            \
            float t0 = uB0 + hsb0;                                            \
            float t1 = uB1 + hsb1;                                            \
            float t2 = uB2 + hsb2;                                            \
            float d0 = fmaf(t0, -inv9, qCb0);                                 \
            float d1 = fmaf(t1, -inv9, qCb1);                                 \
            float d2 = fmaf(t2, -inv9, qCb2);                                 \
            acc += d0*d0 + d1*d1 + d2*d2;                                     \
            cnt += 1u;                                                        \
        }                                                                     \
    }

// u' = v + hs ; v' = hs   (period-2 rotation)
#define ROTATE                                                                \
    uA0 = vA0 + hsa0; uA1 = vA1 + hsa1; uA2 = vA2 + hsa2;                     \
    uB0 = vB0 + hsb0; uB1 = vB1 + hsb1; uB2 = vB2 + hsb2;                     \
    vA0 = hsa0; vA1 = hsa1; vA2 = hsa2;                                       \
    vB0 = hsb0; vB1 = hsb1; vB2 = hsb2;                                       \
    qCa0=qa0; qCa1=qa1; qCa2=qa2; qCb0=qb0; qCb1=qb1; qCb2=qb2;               \
    mCa=ma; mCb=mb;

    if (safe) {
        int off  = (r0 - 1) * W_IMG + colA;
        int off3 = off * 3;
        float2 dv = *reinterpret_cast<const float2*>(depth + off);
        dA_a = dv.x; dA_b = dv.y;
        // warm-up row r0-1 -> v
        { ROW_SAFE;
          vA0=hsa0; vA1=hsa1; vA2=hsa2; vB0=hsb0; vB1=hsb1; vB2=hsb2;
          (void)ma; (void)mb; }
        // warm-up row r0 -> u, v, qC, mC
        { ROW_SAFE;
          uA0 = vA0 + hsa0; uA1 = vA1 + hsa1; uA2 = vA2 + hsa2;
          uB0 = vB0 + hsb0; uB1 = vB1 + hsb1; uB2 = vB2 + hsb2;
          vA0=hsa0; vA1=hsa1; vA2=hsa2; vB0=hsb0; vB1=hsb1; vB2=hsb2;
          qCa0=qa0; qCa1=qa1; qCa2=qa2; qCb0=qb0; qCb1=qb1; qCb2=qb2;
          mCa=ma; mCb=mb; }
        #pragma unroll 2
        for (int r = r0 + 1; r <= rend; ++r) {
            ROW_SAFE;
            EMIT;
            ROTATE;
        }
    } else {
        int off  = (r0 - 1) * W_IMG + colA;
        int off3 = off * 3;
        dA_a = 0.0f; dA_b = 0.0f;
        if (r0 >= 1) {
            if (colinA) dA_a = depth[off];
            if (colinB) dA_b = depth[off + 1];
        }
        { int r = r0 - 1; ROW_GEN;
          vA0=hsa0; vA1=hsa1; vA2=hsa2; vB0=hsb0; vB1=hsb1; vB2=hsb2;
          (void)ma; (void)mb; }
        { int r = r0; ROW_GEN;
          uA0 = vA0 + hsa0; uA1 = vA1 + hsa1; uA2 = vA2 + hsa2;
          uB0 = vB0 + hsb0; uB1 = vB1 + hsb1; uB2 = vB2 + hsb2;
          vA0=hsa0; vA1=hsa1; vA2=hsa2; vB0=hsb0; vB1=hsb1; vB2=hsb2;
          qCa0=qa0; qCa1=qa1; qCa2=qa2; qCb0=qb0; qCb1=qb1; qCb2=qb2;
          mCa=ma; mCb=mb; }
        #pragma unroll 1
        for (int r = r0 + 1; r <= rend; ++r) {
            ROW_GEN;
            EMIT;
            ROTATE;
        }
    }

    // ---- reduction: warp -> block -> global ----
    #pragma unroll
    for (int o = 16; o > 0; o >>= 1) {
        acc += __shfl_down_sync(0xffffffffu, acc, o);
        cnt += __shfl_down_sync(0xffffffffu, cnt, o);
    }
    __shared__ float s_red[WPB];
    __shared__ unsigned int s_redc[WPB];
    if (lane == 0) { s_red[w] = acc; s_redc[w] = cnt; }
    __syncthreads();
    if (tid == 0) {
        float aa = 0.0f; unsigned int cn = 0;
        #pragma unroll
        for (int k = 0; k < WPB; k++) { aa += s_red[k]; cn += s_redc[k]; }
        atomicAdd(&g_num, (double)aa);
        atomicAdd(&g_cnt, cn);
        __threadfence();
        unsigned int t = atomicAdd(&g_ticket, 1u);
        if (t == NBLOCKS - 1) {
            __threadfence();
            double num = g_num;
            unsigned int c2 = g_cnt;
            out[0] = (float)(num / ((double)c2 * 3.0));
            g_num = 0.0;
            g_cnt = 0u;
            g_ticket = 0u;
        }
    }
}

extern "C" void kernel_launch(void* const* d_in, const int* in_sizes, int n_in,
                              void* d_out, int out_size) {
    const float* depth = (const float*)d_in[0];
    const float* rgb   = (const float*)d_in[1];
    const int*   mask  = (const int*)d_in[2];
    const float* l     = (const float*)d_in[3];
    const float* Kc    = (const float*)d_in[4];

    cudaMemcpyToSymbolAsync(c_l,  l,  27 * sizeof(float), 0, cudaMemcpyDeviceToDevice);
    cudaMemcpyToSymbolAsync(c_Kc, Kc,  9 * sizeof(float), 0, cudaMemcpyDeviceToDevice);

    shading_loss_kernel<<<NBLOCKS, NTHREADS>>>(depth, rgb, mask, (float*)d_out);
}

// round 17
// speedup vs baseline: 1.2607x; 1.0124x over previous
#include <cuda_runtime.h>

#define W_IMG 3840
#define H_IMG 2160
#define OUT_W 60             // output columns per warp (lane pairs 1..30)
#define NW_X 64              // 3840 / 60
#define NW_Y 74              // vertical strips (30 or 29 rows)
#define WPB 8
#define NTHREADS 256
#define NBLOCKS ((NW_X * NW_Y) / WPB)   // 592 = 148 SMs x 4 blocks, one wave

__device__ double g_num;
__device__ unsigned int g_cnt;
__device__ unsigned int g_ticket;

__constant__ float c_l[27];
__constant__ float c_Kc[9];

__launch_bounds__(NTHREADS, 4)
__global__ void shading_loss_kernel(const float* __restrict__ depth,
                                    const float* __restrict__ rgb,
                                    const int*   __restrict__ mask,
                                    float* __restrict__ out)
{
    const int tid  = threadIdx.x;
    const int lane = tid & 31;
    const int w    = tid >> 5;
    const int wid  = blockIdx.x * WPB + w;
    const int tx   = wid % NW_X;
    const int ty   = wid / NW_X;
    // 2160 = 14*30 + 60*29 : first 14 strips are 30 rows tall
    const int r0   = ty * 29 + min(ty, 14);
    const int hgt  = 29 + (ty < 14 ? 1 : 0);
    const int c0   = tx * OUT_W;
    const int colA = c0 - 2 + 2 * lane;    // even
    const int colB = colA + 1;
    const bool colinA = (colA >= 0) && (colA < W_IMG);
    const bool colinB = (colB >= 0) && (colB < W_IMG);
    const bool safe   = (tx >= 1) && (tx <= NW_X - 2) && (ty >= 1) && (ty <= NW_Y - 2);

    // camera inverse (adjugate) from constant bank — uniform arithmetic
    float a = c_Kc[0], b = c_Kc[1], cc = c_Kc[2];
    float d = c_Kc[3], e = c_Kc[4], f  = c_Kc[5];
    float g = c_Kc[6], h = c_Kc[7], i  = c_Kc[8];
    float A =  (e*i - f*h), B = -(d*i - f*g), C =  (d*h - e*g);
    float inv = 1.0f / (a*A + b*B + cc*C);
    const float K0 = A*inv,  K1 = -(b*i - cc*h)*inv,  K2 =  (b*f - cc*e)*inv;
    const float K3 = B*inv,  K4 =  (a*i - cc*g)*inv,  K5 = -(a*f - cc*d)*inv;
    const float K6 = C*inv,  K7 = -(a*h - b*g)*inv,   K8 =  (a*e - b*d)*inv;

    // ray for column A at row r0-1
    const float xA = (float)colA;
    const float y0f = (float)(r0 - 1);
    const float Rx = K0 * xA + K1 * y0f + K2;
    const float Ry = K3 * xA + K4 * y0f + K5;
    const float Rz = K6 * xA + K7 * y0f + K8;

    // n = u*[dl(d0-du)] + v*[du(dl-d0)] + w*[dl*du]
    float ux = Ry * K6 - Rz * K3;
    float uy = Rz * K0 - Rx * K6;
    float uz = Rx * K3 - Ry * K0;
    const float wx = K3 * K7 - K6 * K4;
    const float wy = K6 * K1 - K0 * K7;
    const float wz = K0 * K4 - K3 * K1;
    const float vAx = Ry * K7 - Rz * K4;
    const float vAy = Rz * K1 - Rx * K7;
    const float vAz = Rx * K4 - Ry * K1;
    const float vBx = vAx + wx, vBy = vAy + wy, vBz = vAz + wz;

    float acc = 0.0f;
    unsigned int cnt = 0;
    const int eMask = (lane >= 1 && lane <= 30) ? 1 : 0;
    const float inv9 = 1.0f / 9.0f;
    const int rend = r0 + hgt;

    // vertical pipeline state
    float uA0,uA1,uA2, uB0,uB1,uB2;         // h(r-2)+h(r-1)
    float vA0,vA1,vA2, vB0,vB1,vB2;         // h(r-1)
    float qCa0,qCa1,qCa2, qCb0,qCb1,qCb2;   // q(row r-1)
    int   mCa, mCb;                          // emit gates (mask & emitlane)
    float dA_a, dA_b;                        // depth(row r)

#define SHADE1(qq0,qq1,qq2, vx_,vy_,vz_, d0,dl,du, mm_, rr0,rr1,rr2)          \
  {                                                                           \
    float b0=0.f,b1=0.f,b2=0.f;                                               \
    if (mm_) {                                                                \
      float s1 = (dl) * ((d0) - (du));                                        \
      float s2 = (du) * ((dl) - (d0));                                        \
      float s3 = (dl) * (du);                                                 \
      float nx = fmaf(ux, s1, fmaf((vx_), s2, wx * s3));                      \
      float ny = fmaf(uy, s1, fmaf((vy_), s2, wy * s3));                      \
      float nz = fmaf(uz, s1, fmaf((vz_), s2, wz * s3));                      \
      float nn=nx*nx+ny*ny+nz*nz;                                             \
      float invn=rsqrtf(fmaxf(nn,1e-24f));                                    \
      nx*=invn; ny*=invn; nz*=invn;                                           \
      float nx2=nx*nx, ny2=ny*ny, nz2=nz*nz;                                  \
      float H1=ny,H2=nz,H3=nx,H4=nx*ny,H5=ny*nz;                              \
      float H6=2.f*nz2-nx2-ny2, H7=nz*nx, H8=nx2-ny2;                         \
      b0=c_l[0]+H1*c_l[3]+H2*c_l[6]+H3*c_l[9]+H4*c_l[12]+H5*c_l[15]+H6*c_l[18]+H7*c_l[21]+H8*c_l[24]; \
      b1=c_l[1]+H1*c_l[4]+H2*c_l[7]+H3*c_l[10]+H4*c_l[13]+H5*c_l[16]+H6*c_l[19]+H7*c_l[22]+H8*c_l[25]; \
      b2=c_l[2]+H1*c_l[5]+H2*c_l[8]+H3*c_l[11]+H4*c_l[14]+H5*c_l[17]+H6*c_l[20]+H7*c_l[23]+H8*c_l[26]; \
    }                                                                         \
    qq0=b0-(rr0); qq1=b1-(rr1); qq2=b2-(rr2);                                 \
  }

#define ROW_CORE(dBa_, dBb_, ma_, mb_, ra0_,ra1_,ra2_, rb0_,rb1_,rb2_)        \
    float dRa = dA_b;                                                         \
    float dRb = __shfl_down_sync(0xffffffffu, dA_a, 1);                       \
    float qa0,qa1,qa2, qb0,qb1,qb2;                                           \
    SHADE1(qa0,qa1,qa2, vAx,vAy,vAz, dA_a,dRa,(dBa_), ma_, ra0_,ra1_,ra2_);   \
    SHADE1(qb0,qb1,qb2, vBx,vBy,vBz, dA_b,dRb,(dBb_), mb_, rb0_,rb1_,rb2_);   \
    float p0 = qa0+qb0, p1 = qa1+qb1, p2 = qa2+qb2;                           \
    float hsa0 = __shfl_up_sync(0xffffffffu, qb0, 1) + p0;                    \
    float hsa1 = __shfl_up_sync(0xffffffffu, qb1, 1) + p1;                    \
    float hsa2 = __shfl_up_sync(0xffffffffu, qb2, 1) + p2;                    \
    float hsb0 = p0 + __shfl_down_sync(0xffffffffu, qa0, 1);                  \
    float hsb1 = p1 + __shfl_down_sync(0xffffffffu, qa1, 1);                  \
    float hsb2 = p2 + __shfl_down_sync(0xffffffffu, qa2, 1);                  \
    dA_a = (dBa_); dA_b = (dBb_);                                             \
    ux -= wx; uy -= wy; uz -= wz;

#define ROW_SAFE                                                              \
    float2 dBv = *reinterpret_cast<const float2*>(depth + off + W_IMG);       \
    int2   mmv = *reinterpret_cast<const int2*>(mask + off);                  \
    const float* rp = rgb + off3;                                             \
    float2 f0 = *reinterpret_cast<const float2*>(rp);                         \
    float2 f1 = *reinterpret_cast<const float2*>(rp + 2);                     \
    float2 f2 = *reinterpret_cast<const float2*>(rp + 4);                     \
    int ma = mmv.x, mb = mmv.y;   /* mask values are 0/1 */                   \
    ROW_CORE(dBv.x, dBv.y, ma, mb, f0.x,f0.y,f1.x, f1.y,f2.x,f2.y);           \
    off += W_IMG; off3 += 3 * W_IMG;

#define ROW_GEN                                                               \
    const bool rin  = ((unsigned)r < (unsigned)H_IMG);                        \
    const bool rnin = ((unsigned)(r + 1) < (unsigned)H_IMG);                  \
    float dBa = (rnin && colinA) ? depth[off + W_IMG]     : 0.0f;             \
    float dBb = (rnin && colinB) ? depth[off + W_IMG + 1] : 0.0f;             \
    int ma = 0, mb = 0;                                                       \
    float ra0=0.f,ra1=0.f,ra2=0.f, rb0=0.f,rb1=0.f,rb2=0.f;                   \
    if (rin && colinA) { ma = mask[off];                                      \
        ra0 = rgb[off3]; ra1 = rgb[off3+1]; ra2 = rgb[off3+2]; }              \
    if (rin && colinB) { mb = mask[off+1];                                    \
        rb0 = rgb[off3+3]; rb1 = rgb[off3+4]; rb2 = rgb[off3+5]; }            \
    ROW_CORE(dBa, dBb, ma, mb, ra0,ra1,ra2, rb0,rb1,rb2);                     \
    off += W_IMG; off3 += 3 * W_IMG;

// emit row r-1: t = u + hs(current row); gates already include emitlane
#define EMIT                                                                  \
    {                                                                         \
        if (mCa) {                                                            \
            float t0 = uA0 + hsa0;                                            \
            float t1 = uA1 + hsa1;                                            \
            float t2 = uA2 + hsa2;                                            \
            float d0 = fmaf(t0, -inv9, qCa0);                                 \
            float d1 = fmaf(t1, -inv9, qCa1);                                 \
            float d2 = fmaf(t2, -inv9, qCa2);                                 \
            acc += d0*d0 + d1*d1 + d2*d2;                                     \
        }                                                                     \
        if (mCb) {                                                            \
            float t0 = uB0 + hsb0;                                            \
            float t1 = uB1 + hsb1;                                            \
            float t2 = uB2 + hsb2;                                            \
            float d0 = fmaf(t0, -inv9, qCb0);                                 \
            float d1 = fmaf(t1, -inv9, qCb1);                                 \
            float d2 = fmaf(t2, -inv9, qCb2);                                 \
            acc += d0*d0 + d1*d1 + d2*d2;                                     \
        }                                                                     \
        cnt += (unsigned int)(mCa + mCb);                                     \
    }

// u' = v + hs ; v' = hs   (period-2 rotation)
#define ROTATE                                                                \
    uA0 = vA0 + hsa0; uA1 = vA1 + hsa1; uA2 = vA2 + hsa2;                     \
    uB0 = vB0 + hsb0; uB1 = vB1 + hsb1; uB2 = vB2 + hsb2;                     \
    vA0 = hsa0; vA1 = hsa1; vA2 = hsa2;                                       \
    vB0 = hsb0; vB1 = hsb1; vB2 = hsb2;                                       \
    qCa0=qa0; qCa1=qa1; qCa2=qa2; qCb0=qb0; qCb1=qb1; qCb2=qb2;               \
    mCa = ma & eMask; mCb = mb & eMask;

    if (safe) {
        int off  = (r0 - 1) * W_IMG + colA;
        int off3 = off * 3;
        float2 dv = *reinterpret_cast<const float2*>(depth + off);
        dA_a = dv.x; dA_b = dv.y;
        // warm-up row r0-1 -> v
        { ROW_SAFE;
          vA0=hsa0; vA1=hsa1; vA2=hsa2; vB0=hsb0; vB1=hsb1; vB2=hsb2;
          (void)ma; (void)mb; }
        // warm-up row r0 -> u, v, qC, gates
        { ROW_SAFE;
          uA0 = vA0 + hsa0; uA1 = vA1 + hsa1; uA2 = vA2 + hsa2;
          uB0 = vB0 + hsb0; uB1 = vB1 + hsb1; uB2 = vB2 + hsb2;
          vA0=hsa0; vA1=hsa1; vA2=hsa2; vB0=hsb0; vB1=hsb1; vB2=hsb2;
          qCa0=qa0; qCa1=qa1; qCa2=qa2; qCb0=qb0; qCb1=qb1; qCb2=qb2;
          mCa = ma & eMask; mCb = mb & eMask; }
        #pragma unroll 4
        for (int r = r0 + 1; r <= rend; ++r) {
            ROW_SAFE;
            EMIT;
            ROTATE;
        }
    } else {
        int off  = (r0 - 1) * W_IMG + colA;
        int off3 = off * 3;
        dA_a = 0.0f; dA_b = 0.0f;
        if (r0 >= 1) {
            if (colinA) dA_a = depth[off];
            if (colinB) dA_b = depth[off + 1];
        }
        { int r = r0 - 1; ROW_GEN;
          vA0=hsa0; vA1=hsa1; vA2=hsa2; vB0=hsb0; vB1=hsb1; vB2=hsb2;
          (void)ma; (void)mb; }
        { int r = r0; ROW_GEN;
          uA0 = vA0 + hsa0; uA1 = vA1 + hsa1; uA2 = vA2 + hsa2;
          uB0 = vB0 + hsb0; uB1 = vB1 + hsb1; uB2 = vB2 + hsb2;
          vA0=hsa0; vA1=hsa1; vA2=hsa2; vB0=hsb0; vB1=hsb1; vB2=hsb2;
          qCa0=qa0; qCa1=qa1; qCa2=qa2; qCb0=qb0; qCb1=qb1; qCb2=qb2;
          mCa = ma & eMask; mCb = mb & eMask; }
        #pragma unroll 1
        for (int r = r0 + 1; r <= rend; ++r) {
            ROW_GEN;
            EMIT;
            ROTATE;
        }
    }

    // ---- reduction: warp -> block -> global ----
    #pragma unroll
    for (int o = 16; o > 0; o >>= 1) {
        acc += __shfl_down_sync(0xffffffffu, acc, o);
        cnt += __shfl_down_sync(0xffffffffu, cnt, o);
    }
    __shared__ float s_red[WPB];
    __shared__ unsigned int s_redc[WPB];
    if (lane == 0) { s_red[w] = acc; s_redc[w] = cnt; }
    __syncthreads();
    if (tid == 0) {
        float aa = 0.0f; unsigned int cn = 0;
        #pragma unroll
        for (int k = 0; k < WPB; k++) { aa += s_red[k]; cn += s_redc[k]; }
        atomicAdd(&g_num, (double)aa);
        atomicAdd(&g_cnt, cn);
        __threadfence();
        unsigned int t = atomicAdd(&g_ticket, 1u);
        if (t == NBLOCKS - 1) {
            __threadfence();
            double num = g_num;
            unsigned int c2 = g_cnt;
            out[0] = (float)(num / ((double)c2 * 3.0));
            g_num = 0.0;
            g_cnt = 0u;
            g_ticket = 0u;
        }
    }
}

extern "C" void kernel_launch(void* const* d_in, const int* in_sizes, int n_in,
                              void* d_out, int out_size) {
    const float* depth = (const float*)d_in[0];
    const float* rgb   = (const float*)d_in[1];
    const int*   mask  = (const int*)d_in[2];
    const float* l     = (const float*)d_in[3];
    const float* Kc    = (const float*)d_in[4];

    cudaMemcpyToSymbolAsync(c_l,  l,  27 * sizeof(float), 0, cudaMemcpyDeviceToDevice);
    cudaMemcpyToSymbolAsync(c_Kc, Kc,  9 * sizeof(float), 0, cudaMemcpyDeviceToDevice);

    shading_loss_kernel<<<NBLOCKS, NTHREADS>>>(depth, rgb, mask, (float*)d_out);
}